// round 16
// baseline (speedup 1.0000x reference)
#include <cuda_runtime.h>
#include <cuda_fp16.h>

#define NN 50000
#define EE 800000
#define DD 128
#define HH 128
#define GG 256

typedef unsigned long long ull;

// Scratch (__device__ globals — no allocs allowed). Statically zeroed at load;
// g_indeg is re-zeroed inside k_scan_fill each launch (replay-invariant).
__device__ int    g_indeg[NN];
__device__ float  g_dinv[NN];
__device__ int    g_row_off[NN + 1];
__device__ int    g_cursor[NN];
__device__ int    g_csr_src[EE];
__device__ __half g_zws[(size_t)NN * HH];   // fp16: dinv[i] * (z @ W)[i]
__device__ float  g_z1[(size_t)NN * HH];    // layer-1 output (fp32)
__device__ __half g_z16[(size_t)NN * HH];   // fp16 copy of z1 (layer-2 GEMM input)
__device__ __half g_w16[2][DD * HH];        // fp16 W1, W2
__device__ int    g_gstart[GG + 1];         // per-graph node ranges (batch sorted)

#define SCAN_B 256
#define SCAN_NB ((NN + SCAN_B - 1) / SCAN_B)  // 196
__device__ int g_bsum[SCAN_NB];

// ---------------------------------------------------------------------------
// PTX helpers
// ---------------------------------------------------------------------------
__device__ __forceinline__ unsigned smem_u32(const void* p) {
    unsigned r;
    asm("{ .reg .u64 t; cvta.to.shared.u64 t, %1; cvt.u32.u64 %0, t; }"
        : "=r"(r) : "l"(p));
    return r;
}
#define LDSM_X4(r, addr)                                                       \
    asm volatile("ldmatrix.sync.aligned.m8n8.x4.shared.b16 {%0,%1,%2,%3}, [%4];" \
                 : "=r"(r[0]), "=r"(r[1]), "=r"(r[2]), "=r"(r[3]) : "r"(addr))
#define LDSM_X4_T(r, addr)                                                     \
    asm volatile("ldmatrix.sync.aligned.m8n8.x4.trans.shared.b16 {%0,%1,%2,%3}, [%4];" \
                 : "=r"(r[0]), "=r"(r[1]), "=r"(r[2]), "=r"(r[3]) : "r"(addr))
#define MMA_F16(d, a, b0, b1)                                                  \
    asm volatile("mma.sync.aligned.m16n8k16.row.col.f32.f16.f16.f32 "          \
                 "{%0,%1,%2,%3},{%4,%5,%6,%7},{%8,%9},{%0,%1,%2,%3};"          \
                 : "+f"(d[0]), "+f"(d[1]), "+f"(d[2]), "+f"(d[3])              \
                 : "r"(a[0]), "r"(a[1]), "r"(a[2]), "r"(a[3]), "r"(b0), "r"(b1))

// ---------------------------------------------------------------------------
// Setup
// ---------------------------------------------------------------------------
__global__ void k_deg(const int* __restrict__ dst) {
    int e = blockIdx.x * blockDim.x + threadIdx.x;
    if (e < EE) atomicAdd(&g_indeg[dst[e]], 1);
}

__global__ void k_dinv() {
    int i = blockIdx.x * blockDim.x + threadIdx.x;
    if (i < NN) g_dinv[i] = rsqrtf((float)g_indeg[i] + 1.0f);  // +1 self-loop
}

// Convert W1,W2 to fp16 once. 2*16384 floats, 8 per thread -> 16 blocks.
__global__ void k_wcvt(const float* __restrict__ W1, const float* __restrict__ W2) {
    int ci = blockIdx.x * blockDim.x + threadIdx.x;  // chunk of 8 floats
    const float* src = (ci < 2048) ? W1 : W2;
    int off = (ci & 2047) * 8;
    const float4* p = (const float4*)(src + off);
    float4 v0 = __ldg(p);
    float4 v1 = __ldg(p + 1);
    __half2 h0 = __floats2half2_rn(v0.x, v0.y);
    __half2 h1 = __floats2half2_rn(v0.z, v0.w);
    __half2 h2 = __floats2half2_rn(v1.x, v1.y);
    __half2 h3 = __floats2half2_rn(v1.z, v1.w);
    uint4 u;
    u.x = *(unsigned*)&h0; u.y = *(unsigned*)&h1;
    u.z = *(unsigned*)&h2; u.w = *(unsigned*)&h3;
    *(uint4*)&g_w16[ci >= 2048][off] = u;
}

__global__ void k_gstart(const int* __restrict__ batch) {
    int g = threadIdx.x;  // 0..255
    int lo = 0, hi = NN;
    while (lo < hi) {
        int m = (lo + hi) >> 1;
        if (batch[m] < g) lo = m + 1; else hi = m;
    }
    g_gstart[g] = lo;
    if (g == 0) g_gstart[GG] = NN;
}

__global__ void __launch_bounds__(SCAN_B) k_scan_block() {
    __shared__ int sh[SCAN_B];
    int i = blockIdx.x * SCAN_B + threadIdx.x;
    int v = (i < NN) ? g_indeg[i] : 0;
    sh[threadIdx.x] = v;
    __syncthreads();
    for (int off = SCAN_B / 2; off > 0; off >>= 1) {
        if (threadIdx.x < off) sh[threadIdx.x] += sh[threadIdx.x + off];
        __syncthreads();
    }
    if (threadIdx.x == 0) g_bsum[blockIdx.x] = sh[0];
}

// Fused: block offset + in-block scan + row_off/cursor writes + indeg reset.
__global__ void __launch_bounds__(SCAN_B) k_scan_fill() {
    __shared__ int red[SCAN_B];
    __shared__ int sh[SCAN_B];
    const int bid = blockIdx.x;
    const int t = threadIdx.x;

    red[t] = (t < bid) ? g_bsum[t] : 0;   // bid <= 195 < 256
    __syncthreads();
    for (int off = SCAN_B / 2; off > 0; off >>= 1) {
        if (t < off) red[t] += red[t + off];
        __syncthreads();
    }
    const int boff = red[0];

    int i = bid * SCAN_B + t;
    int v = (i < NN) ? g_indeg[i] : 0;
    sh[t] = v;
    __syncthreads();
    for (int off = 1; off < SCAN_B; off <<= 1) {
        int u = (t >= off) ? sh[t - off] : 0;
        __syncthreads();
        sh[t] += u;
        __syncthreads();
    }
    if (i < NN) {
        int excl = boff + sh[t] - v;
        g_row_off[i] = excl;
        g_cursor[i] = excl;
        g_indeg[i] = 0;  // reset for next replay
    }
    if (bid == 0 && t == 0) g_row_off[NN] = EE;
}

__global__ void k_fill(const int* __restrict__ src, const int* __restrict__ dst) {
    int e = blockIdx.x * blockDim.x + threadIdx.x;
    if (e < EE) {
        int p = atomicAdd(&g_cursor[dst[e]], 1);
        g_csr_src[p] = src[e];
    }
}

// ---------------------------------------------------------------------------
// GEMM (fp16 HMMA + ldmatrix): g_zws(fp16) = dinv[:,None] * (A @ W16).
// Block: 64 rows x 128 cols, 256 thr, 48 KB smem (3 CTAs/SM).
// AF16: A already fp16 (pure copy staging); else fp32 + convert.
// Swizzle: 16B chunk index ^= (row & 7)  -> conflict-free LDSM.
// ---------------------------------------------------------------------------
#define GEMM_M 64
template <bool AF16>
__global__ void __launch_bounds__(256) k_gemm(const void* __restrict__ Ain,
                                              const __half* __restrict__ W16) {
    __shared__ __half a_sm[GEMM_M * 128];  // 16 KB
    __shared__ __half w_sm[128 * 128];     // 32 KB

    const int t = threadIdx.x;
    const int row0 = blockIdx.x * GEMM_M;

    // Stage A: 1024 16B-chunks (8 halves each), 4 per thread.
#pragma unroll
    for (int j = 0; j < 4; j++) {
        int ci = t + 256 * j;
        int r = ci >> 4, c8 = ci & 15;
        int gr = row0 + r; if (gr >= NN) gr = NN - 1;
        uint4 u;
        if (AF16) {
            u = __ldg((const uint4*)((const __half*)Ain + (size_t)gr * 128 + c8 * 8));
        } else {
            const float4* p = (const float4*)((const float*)Ain + (size_t)gr * 128 + c8 * 8);
            float4 v0 = __ldg(p);
            float4 v1 = __ldg(p + 1);
            __half2 h0 = __floats2half2_rn(v0.x, v0.y);
            __half2 h1 = __floats2half2_rn(v0.z, v0.w);
            __half2 h2 = __floats2half2_rn(v1.x, v1.y);
            __half2 h3 = __floats2half2_rn(v1.z, v1.w);
            u.x = *(unsigned*)&h0; u.y = *(unsigned*)&h1;
            u.z = *(unsigned*)&h2; u.w = *(unsigned*)&h3;
        }
        *(uint4*)&a_sm[r * 128 + (c8 ^ (r & 7)) * 8] = u;
    }
    // Stage W: 2048 chunks, pure fp16 copy, 8 per thread.
#pragma unroll
    for (int j = 0; j < 8; j++) {
        int ci = t + 256 * j;
        int r = ci >> 4, c8 = ci & 15;
        uint4 u = __ldg((const uint4*)(W16 + (size_t)r * 128 + c8 * 8));
        *(uint4*)&w_sm[r * 128 + (c8 ^ (r & 7)) * 8] = u;
    }
    __syncthreads();

    const int w = t >> 5, lane = t & 31;
    const int wm = (w & 3) * 16;   // warp rows: wm..wm+15
    const int wn = (w >> 2) * 64;  // warp cols: wn..wn+63
    const int q = lane >> 3;       // ldmatrix address group 0..3
    const int lr = lane & 7;

    float acc[8][4];
#pragma unroll
    for (int nt = 0; nt < 8; nt++)
#pragma unroll
        for (int i = 0; i < 4; i++) acc[nt][i] = 0.0f;

#pragma unroll
    for (int ks = 0; ks < 8; ks++) {
        const int k0 = ks * 16;
        unsigned a[4];
        {
            int r = wm + lr + ((q & 1) << 3);
            int c8 = (k0 >> 3) + (q >> 1);
            LDSM_X4(a, smem_u32(&a_sm[r * 128 + (c8 ^ (r & 7)) * 8]));
        }
        unsigned b[4][4];
#pragma unroll
        for (int p = 0; p < 4; p++) {
            int r = k0 + lr + ((q & 1) << 3);
            int c8 = ((wn + p * 16) >> 3) + (q >> 1);
            LDSM_X4_T(b[p], smem_u32(&w_sm[r * 128 + (c8 ^ (r & 7)) * 8]));
        }
#pragma unroll
        for (int p = 0; p < 4; p++) {
            MMA_F16(acc[2 * p],     a, b[p][0], b[p][1]);
            MMA_F16(acc[2 * p + 1], a, b[p][2], b[p][3]);
        }
    }

    // Epilogue: scale by dinv, convert fp16, store pairs.
    const int g = lane >> 2, ti = lane & 3;
    int ra = row0 + wm + g;
    int rb = ra + 8;
    float dia = (ra < NN) ? g_dinv[ra] : 0.0f;
    float dib = (rb < NN) ? g_dinv[rb] : 0.0f;
    unsigned* zz = (unsigned*)g_zws;  // half2 granularity, pitch 64
#pragma unroll
    for (int nt = 0; nt < 8; nt++) {
        int colh = (wn + nt * 8) >> 1;
        if (ra < NN) {
            __half2 h = __floats2half2_rn(acc[nt][0] * dia, acc[nt][1] * dia);
            zz[(size_t)ra * 64 + colh + ti] = *(unsigned*)&h;
        }
        if (rb < NN) {
            __half2 h = __floats2half2_rn(acc[nt][2] * dib, acc[nt][3] * dib);
            zz[(size_t)rb * 64 + colh + ti] = *(unsigned*)&h;
        }
    }
}

// ---------------------------------------------------------------------------
// Gather + epilogue (no atomics): one warp per dst node, MLP-2, 128-thr blocks.
// Writes fp32 z and (optionally) fp16 copy for the next GEMM's A staging.
// ---------------------------------------------------------------------------
__device__ __forceinline__ void acc_h4(float4& a, uint2 u) {
    float2 f0 = __half22float2(*(__half2*)&u.x);
    float2 f1 = __half22float2(*(__half2*)&u.y);
    a.x += f0.x; a.y += f0.y; a.z += f1.x; a.w += f1.y;
}

template <bool WRITE_F16>
__global__ void __launch_bounds__(128) k_gather(const float* __restrict__ b,
                                                const float* __restrict__ alpha,
                                                float* __restrict__ zout) {
    int d = blockIdx.x * 4 + (threadIdx.x >> 5);
    if (d >= NN) return;
    int lane = threadIdx.x & 31;

    const uint2* zz = (const uint2*)g_zws;
    int beg = g_row_off[d];
    int end = g_row_off[d + 1];

    float4 acc = make_float4(0.f, 0.f, 0.f, 0.f);
    float4 acc2 = make_float4(0.f, 0.f, 0.f, 0.f);
    acc_h4(acc, __ldg(&zz[(size_t)d * 32 + lane]));  // self-loop term

    int e = beg;
    for (; e + 1 < end; e += 2) {
        int s0 = g_csr_src[e];
        int s1 = g_csr_src[e + 1];
        uint2 v0 = __ldg(&zz[(size_t)s0 * 32 + lane]);
        uint2 v1 = __ldg(&zz[(size_t)s1 * 32 + lane]);
        acc_h4(acc, v0);
        acc_h4(acc2, v1);
    }
    if (e < end) {
        int s0 = g_csr_src[e];
        acc_h4(acc, __ldg(&zz[(size_t)s0 * 32 + lane]));
    }
    acc.x += acc2.x; acc.y += acc2.y; acc.z += acc2.z; acc.w += acc2.w;

    float di = g_dinv[d];
    float4 bb = __ldg(&((const float4*)b)[lane]);
    float4 al = __ldg(&((const float4*)alpha)[lane]);
    float4 h;
    h.x = di * acc.x + bb.x; h.x = (h.x > 0.f) ? h.x : al.x * h.x;
    h.y = di * acc.y + bb.y; h.y = (h.y > 0.f) ? h.y : al.y * h.y;
    h.z = di * acc.z + bb.z; h.z = (h.z > 0.f) ? h.z : al.z * h.z;
    h.w = di * acc.w + bb.w; h.w = (h.w > 0.f) ? h.w : al.w * h.w;

    ((float4*)zout)[(size_t)d * 32 + lane] = h;
    if (WRITE_F16) {
        __half2 p0 = __floats2half2_rn(h.x, h.y);
        __half2 p1 = __floats2half2_rn(h.z, h.w);
        uint2 u;
        u.x = *(unsigned*)&p0; u.y = *(unsigned*)&p1;
        ((uint2*)g_z16)[(size_t)d * 32 + lane] = u;
    }
}

// ---------------------------------------------------------------------------
// Pool: segment sums over sorted batch (no atomics).
// ---------------------------------------------------------------------------
__global__ void __launch_bounds__(128) k_pool(const float* __restrict__ z1,
                                              const float* __restrict__ z2,
                                              float* __restrict__ pool) {
    int blk = blockIdx.x;
    int g = (blk < GG) ? blk : blk - GG;
    const float* z = (blk < GG) ? z1 : z2;
    int off = (blk < GG) ? 0 : HH;
    int c = threadIdx.x;

    int i0 = g_gstart[g];
    int i1 = g_gstart[g + 1];
    float s = 0.f, s2 = 0.f;
    int i = i0;
    for (; i + 1 < i1; i += 2) {
        s += z[(size_t)i * HH + c];
        s2 += z[(size_t)(i + 1) * HH + c];
    }
    if (i < i1) s += z[(size_t)i * HH + c];
    pool[(size_t)g * (2 * HH) + off + c] = s + s2;
}

// ---------------------------------------------------------------------------
extern "C" void kernel_launch(void* const* d_in, const int* in_sizes, int n_in,
                              void* d_out, int out_size) {
    const float* x     = (const float*)d_in[0];
    const int*   eidx  = (const int*)d_in[1];
    const int*   batch = (const int*)d_in[2];
    const float* W1    = (const float*)d_in[3];
    const float* b1    = (const float*)d_in[4];
    const float* W2    = (const float*)d_in[5];
    const float* b2    = (const float*)d_in[6];
    const float* alpha = (const float*)d_in[7];

    const int* src = eidx;       // edge_index[0]
    const int* dst = eidx + EE;  // edge_index[1]

    float* out  = (float*)d_out;
    float* pool = out + (size_t)NN * HH;

    float* z1;
    cudaGetSymbolAddress((void**)&z1, g_z1);
    __half* w16_0;
    cudaGetSymbolAddress((void**)&w16_0, g_w16);
    __half* z16;
    cudaGetSymbolAddress((void**)&z16, g_z16);

    const int GEMM_GRID = (NN + GEMM_M - 1) / GEMM_M;  // 782

    // g_indeg is zero on entry (static init / reset inside k_scan_fill)
    k_deg<<<(EE + 255) / 256, 256>>>(dst);                    // 0
    k_dinv<<<(NN + 255) / 256, 256>>>();                      // 1
    k_wcvt<<<16, 256>>>(W1, W2);                              // 2
    k_gemm<false><<<GEMM_GRID, 256>>>(x, w16_0);              // 3  <- ncu probe
    k_gstart<<<1, 256>>>(batch);                              // 4
    k_scan_block<<<SCAN_NB, SCAN_B>>>();                      // 5
    k_scan_fill<<<SCAN_NB, SCAN_B>>>();                       // 6
    k_fill<<<(EE + 255) / 256, 256>>>(src, dst);              // 7
    k_gather<true><<<(NN + 3) / 4, 128>>>(b1, alpha, z1);     // 8
    k_gemm<true><<<GEMM_GRID, 256>>>(z16, w16_0 + DD * HH);   // 9
    k_gather<false><<<(NN + 3) / 4, 128>>>(b2, alpha, out);   // 10
    k_pool<<<2 * GG, 128>>>(z1, out, pool);                   // 11
}

// round 17
// speedup vs baseline: 1.0344x; 1.0344x over previous
#include <cuda_runtime.h>
#include <cuda_fp16.h>

#define NN 50000
#define EE 800000
#define DD 128
#define HH 128
#define GG 256

typedef unsigned long long ull;

// Scratch (__device__ globals — no allocs allowed). Statically zeroed at load;
// g_indeg is re-zeroed inside k_scan_fill each launch (replay-invariant).
__device__ int    g_indeg[NN];
__device__ float  g_dinv[NN];
__device__ int    g_row_off[NN + 1];
__device__ int    g_cursor[NN];
__device__ int    g_csr_src[EE];
__device__ __half g_zws[(size_t)NN * HH];   // fp16: (z @ W), NO dinv (graph-independent)
__device__ float  g_z1[(size_t)NN * HH];    // layer-1 output (fp32)
__device__ __half g_w16[2][DD * HH];        // fp16 W1, W2
__device__ int    g_gstart[GG + 1];         // per-graph node ranges (batch sorted)

#define SCAN_B 256
#define SCAN_NB ((NN + SCAN_B - 1) / SCAN_B)  // 196
__device__ int g_bsum[SCAN_NB];

// ---------------------------------------------------------------------------
// PTX helpers
// ---------------------------------------------------------------------------
__device__ __forceinline__ unsigned smem_u32(const void* p) {
    unsigned r;
    asm("{ .reg .u64 t; cvta.to.shared.u64 t, %1; cvt.u32.u64 %0, t; }"
        : "=r"(r) : "l"(p));
    return r;
}
#define LDSM_X4(r, addr)                                                       \
    asm volatile("ldmatrix.sync.aligned.m8n8.x4.shared.b16 {%0,%1,%2,%3}, [%4];" \
                 : "=r"(r[0]), "=r"(r[1]), "=r"(r[2]), "=r"(r[3]) : "r"(addr))
#define LDSM_X4_T(r, addr)                                                     \
    asm volatile("ldmatrix.sync.aligned.m8n8.x4.trans.shared.b16 {%0,%1,%2,%3}, [%4];" \
                 : "=r"(r[0]), "=r"(r[1]), "=r"(r[2]), "=r"(r[3]) : "r"(addr))
#define MMA_F16(d, a, b0, b1)                                                  \
    asm volatile("mma.sync.aligned.m16n8k16.row.col.f32.f16.f16.f32 "          \
                 "{%0,%1,%2,%3},{%4,%5,%6,%7},{%8,%9},{%0,%1,%2,%3};"          \
                 : "+f"(d[0]), "+f"(d[1]), "+f"(d[2]), "+f"(d[3])              \
                 : "r"(a[0]), "r"(a[1]), "r"(a[2]), "r"(a[3]), "r"(b0), "r"(b1))

// ---------------------------------------------------------------------------
// Setup
// ---------------------------------------------------------------------------
__global__ void k_deg(const int* __restrict__ dst) {
    int e = blockIdx.x * blockDim.x + threadIdx.x;
    if (e < EE) atomicAdd(&g_indeg[dst[e]], 1);
}

// Block sums of indeg + dinv (fused; reads indeg anyway).
__global__ void __launch_bounds__(SCAN_B) k_scan_block() {
    __shared__ int sh[SCAN_B];
    int i = blockIdx.x * SCAN_B + threadIdx.x;
    int v = (i < NN) ? g_indeg[i] : 0;
    if (i < NN) g_dinv[i] = rsqrtf((float)v + 1.0f);  // +1 self-loop
    sh[threadIdx.x] = v;
    __syncthreads();
    for (int off = SCAN_B / 2; off > 0; off >>= 1) {
        if (threadIdx.x < off) sh[threadIdx.x] += sh[threadIdx.x + off];
        __syncthreads();
    }
    if (threadIdx.x == 0) g_bsum[blockIdx.x] = sh[0];
}

// Fused: block offset + in-block scan + row_off/cursor writes + indeg reset.
__global__ void __launch_bounds__(SCAN_B) k_scan_fill() {
    __shared__ int red[SCAN_B];
    __shared__ int sh[SCAN_B];
    const int bid = blockIdx.x;
    const int t = threadIdx.x;

    red[t] = (t < bid) ? g_bsum[t] : 0;   // bid <= 195 < 256
    __syncthreads();
    for (int off = SCAN_B / 2; off > 0; off >>= 1) {
        if (t < off) red[t] += red[t + off];
        __syncthreads();
    }
    const int boff = red[0];

    int i = bid * SCAN_B + t;
    int v = (i < NN) ? g_indeg[i] : 0;
    sh[t] = v;
    __syncthreads();
    for (int off = 1; off < SCAN_B; off <<= 1) {
        int u = (t >= off) ? sh[t - off] : 0;
        __syncthreads();
        sh[t] += u;
        __syncthreads();
    }
    if (i < NN) {
        int excl = boff + sh[t] - v;
        g_row_off[i] = excl;
        g_cursor[i] = excl;
        g_indeg[i] = 0;  // reset for next replay
    }
    if (bid == 0 && t == 0) g_row_off[NN] = EE;
}

__global__ void k_fill(const int* __restrict__ src, const int* __restrict__ dst) {
    int e = blockIdx.x * blockDim.x + threadIdx.x;
    if (e < EE) {
        int p = atomicAdd(&g_cursor[dst[e]], 1);
        g_csr_src[p] = src[e];
    }
}

// Side-stream: W1,W2 -> fp16 (blocks 0..15) + per-graph starts (block 16).
__global__ void k_wcvt_gstart(const float* __restrict__ W1,
                              const float* __restrict__ W2,
                              const int* __restrict__ batch) {
    if (blockIdx.x == 16) {
        int g = threadIdx.x;  // 0..255
        int lo = 0, hi = NN;
        while (lo < hi) {
            int m = (lo + hi) >> 1;
            if (batch[m] < g) lo = m + 1; else hi = m;
        }
        g_gstart[g] = lo;
        if (g == 0) g_gstart[GG] = NN;
        return;
    }
    int ci = blockIdx.x * blockDim.x + threadIdx.x;  // chunk of 8 floats
    const float* srcp = (ci < 2048) ? W1 : W2;
    int off = (ci & 2047) * 8;
    const float4* p = (const float4*)(srcp + off);
    float4 v0 = __ldg(p);
    float4 v1 = __ldg(p + 1);
    __half2 h0 = __floats2half2_rn(v0.x, v0.y);
    __half2 h1 = __floats2half2_rn(v0.z, v0.w);
    __half2 h2 = __floats2half2_rn(v1.x, v1.y);
    __half2 h3 = __floats2half2_rn(v1.z, v1.w);
    uint4 u;
    u.x = *(unsigned*)&h0; u.y = *(unsigned*)&h1;
    u.z = *(unsigned*)&h2; u.w = *(unsigned*)&h3;
    *(uint4*)&g_w16[ci >= 2048][off] = u;
}

// ---------------------------------------------------------------------------
// GEMM (fp16 HMMA + ldmatrix): g_zws(fp16) = A @ W16  (no dinv — graph-free).
// Block: 64 rows x 128 cols, 256 thr, 48 KB smem. A fp32 converted in-flight.
// Swizzle: 16B chunk index ^= (row & 7)  -> conflict-free LDSM.
// ---------------------------------------------------------------------------
#define GEMM_M 64
__global__ void __launch_bounds__(256) k_gemm(const float* __restrict__ A,
                                              const __half* __restrict__ W16) {
    __shared__ __half a_sm[GEMM_M * 128];  // 16 KB
    __shared__ __half w_sm[128 * 128];     // 32 KB

    const int t = threadIdx.x;
    const int row0 = blockIdx.x * GEMM_M;

    // Stage A: 1024 16B-chunks, 4 per thread (fp32 -> fp16).
#pragma unroll
    for (int j = 0; j < 4; j++) {
        int ci = t + 256 * j;
        int r = ci >> 4, c8 = ci & 15;
        int gr = row0 + r; if (gr >= NN) gr = NN - 1;
        const float4* p = (const float4*)(A + (size_t)gr * 128 + c8 * 8);
        float4 v0 = __ldg(p);
        float4 v1 = __ldg(p + 1);
        __half2 h0 = __floats2half2_rn(v0.x, v0.y);
        __half2 h1 = __floats2half2_rn(v0.z, v0.w);
        __half2 h2 = __floats2half2_rn(v1.x, v1.y);
        __half2 h3 = __floats2half2_rn(v1.z, v1.w);
        uint4 u;
        u.x = *(unsigned*)&h0; u.y = *(unsigned*)&h1;
        u.z = *(unsigned*)&h2; u.w = *(unsigned*)&h3;
        *(uint4*)&a_sm[r * 128 + (c8 ^ (r & 7)) * 8] = u;
    }
    // Stage W: 2048 chunks, pure fp16 copy, 8 per thread.
#pragma unroll
    for (int j = 0; j < 8; j++) {
        int ci = t + 256 * j;
        int r = ci >> 4, c8 = ci & 15;
        uint4 u = __ldg((const uint4*)(W16 + (size_t)r * 128 + c8 * 8));
        *(uint4*)&w_sm[r * 128 + (c8 ^ (r & 7)) * 8] = u;
    }
    __syncthreads();

    const int w = t >> 5, lane = t & 31;
    const int wm = (w & 3) * 16;   // warp rows: wm..wm+15
    const int wn = (w >> 2) * 64;  // warp cols: wn..wn+63
    const int q = lane >> 3;
    const int lr = lane & 7;

    float acc[8][4];
#pragma unroll
    for (int nt = 0; nt < 8; nt++)
#pragma unroll
        for (int i = 0; i < 4; i++) acc[nt][i] = 0.0f;

#pragma unroll
    for (int ks = 0; ks < 8; ks++) {
        const int k0 = ks * 16;
        unsigned a[4];
        {
            int r = wm + lr + ((q & 1) << 3);
            int c8 = (k0 >> 3) + (q >> 1);
            LDSM_X4(a, smem_u32(&a_sm[r * 128 + (c8 ^ (r & 7)) * 8]));
        }
        unsigned b[4][4];
#pragma unroll
        for (int p = 0; p < 4; p++) {
            int r = k0 + lr + ((q & 1) << 3);
            int c8 = ((wn + p * 16) >> 3) + (q >> 1);
            LDSM_X4_T(b[p], smem_u32(&w_sm[r * 128 + (c8 ^ (r & 7)) * 8]));
        }
#pragma unroll
        for (int p = 0; p < 4; p++) {
            MMA_F16(acc[2 * p],     a, b[p][0], b[p][1]);
            MMA_F16(acc[2 * p + 1], a, b[p][2], b[p][3]);
        }
    }

    // Epilogue: convert fp16, store pairs (no dinv).
    const int g = lane >> 2, ti = lane & 3;
    int ra = row0 + wm + g;
    int rb = ra + 8;
    unsigned* zz = (unsigned*)g_zws;  // half2 granularity, pitch 64
#pragma unroll
    for (int nt = 0; nt < 8; nt++) {
        int colh = (wn + nt * 8) >> 1;
        if (ra < NN) {
            __half2 h = __floats2half2_rn(acc[nt][0], acc[nt][1]);
            zz[(size_t)ra * 64 + colh + ti] = *(unsigned*)&h;
        }
        if (rb < NN) {
            __half2 h = __floats2half2_rn(acc[nt][2], acc[nt][3]);
            zz[(size_t)rb * 64 + colh + ti] = *(unsigned*)&h;
        }
    }
}

// ---------------------------------------------------------------------------
// Gather + epilogue (no atomics): one warp per dst node, MLP-2.
// Edge terms weighted by dinv[src] (zws is raw z@W now).
// ---------------------------------------------------------------------------
__device__ __forceinline__ void fma_h4(float4& a, uint2 u, float w) {
    float2 f0 = __half22float2(*(__half2*)&u.x);
    float2 f1 = __half22float2(*(__half2*)&u.y);
    a.x = fmaf(f0.x, w, a.x); a.y = fmaf(f0.y, w, a.y);
    a.z = fmaf(f1.x, w, a.z); a.w = fmaf(f1.y, w, a.w);
}

__global__ void __launch_bounds__(128) k_gather(const float* __restrict__ b,
                                                const float* __restrict__ alpha,
                                                float* __restrict__ zout) {
    int d = blockIdx.x * 4 + (threadIdx.x >> 5);
    if (d >= NN) return;
    int lane = threadIdx.x & 31;

    const uint2* zz = (const uint2*)g_zws;
    int beg = g_row_off[d];
    int end = g_row_off[d + 1];
    float di = g_dinv[d];

    float4 acc = make_float4(0.f, 0.f, 0.f, 0.f);
    float4 acc2 = make_float4(0.f, 0.f, 0.f, 0.f);
    fma_h4(acc, __ldg(&zz[(size_t)d * 32 + lane]), di);  // self-loop: dinv[d]*zw[d]

    int e = beg;
    for (; e + 1 < end; e += 2) {
        int s0 = g_csr_src[e];
        int s1 = g_csr_src[e + 1];
        float w0 = __ldg(&g_dinv[s0]);
        float w1 = __ldg(&g_dinv[s1]);
        uint2 v0 = __ldg(&zz[(size_t)s0 * 32 + lane]);
        uint2 v1 = __ldg(&zz[(size_t)s1 * 32 + lane]);
        fma_h4(acc, v0, w0);
        fma_h4(acc2, v1, w1);
    }
    if (e < end) {
        int s0 = g_csr_src[e];
        fma_h4(acc, __ldg(&zz[(size_t)s0 * 32 + lane]), __ldg(&g_dinv[s0]));
    }
    acc.x += acc2.x; acc.y += acc2.y; acc.z += acc2.z; acc.w += acc2.w;

    float4 bb = __ldg(&((const float4*)b)[lane]);
    float4 al = __ldg(&((const float4*)alpha)[lane]);
    float4 h;
    h.x = di * acc.x + bb.x; h.x = (h.x > 0.f) ? h.x : al.x * h.x;
    h.y = di * acc.y + bb.y; h.y = (h.y > 0.f) ? h.y : al.y * h.y;
    h.z = di * acc.z + bb.z; h.z = (h.z > 0.f) ? h.z : al.z * h.z;
    h.w = di * acc.w + bb.w; h.w = (h.w > 0.f) ? h.w : al.w * h.w;

    ((float4*)zout)[(size_t)d * 32 + lane] = h;
}

// ---------------------------------------------------------------------------
// Pool: segment sum for ONE layer half (GG blocks). No atomics.
// ---------------------------------------------------------------------------
__global__ void __launch_bounds__(128) k_pool(const float* __restrict__ z,
                                              float* __restrict__ pool,
                                              int off) {
    int g = blockIdx.x;
    int c = threadIdx.x;
    int i0 = g_gstart[g];
    int i1 = g_gstart[g + 1];
    float s = 0.f, s2 = 0.f;
    int i = i0;
    for (; i + 1 < i1; i += 2) {
        s += z[(size_t)i * HH + c];
        s2 += z[(size_t)(i + 1) * HH + c];
    }
    if (i < i1) s += z[(size_t)i * HH + c];
    pool[(size_t)g * (2 * HH) + off + c] = s + s2;
}

// ---------------------------------------------------------------------------
extern "C" void kernel_launch(void* const* d_in, const int* in_sizes, int n_in,
                              void* d_out, int out_size) {
    const float* x     = (const float*)d_in[0];
    const int*   eidx  = (const int*)d_in[1];
    const int*   batch = (const int*)d_in[2];
    const float* W1    = (const float*)d_in[3];
    const float* b1    = (const float*)d_in[4];
    const float* W2    = (const float*)d_in[5];
    const float* b2    = (const float*)d_in[6];
    const float* alpha = (const float*)d_in[7];

    const int* src = eidx;       // edge_index[0]
    const int* dst = eidx + EE;  // edge_index[1]

    float* out  = (float*)d_out;
    float* pool = out + (size_t)NN * HH;

    float* z1;
    cudaGetSymbolAddress((void**)&z1, g_z1);
    __half* w16_0;
    cudaGetSymbolAddress((void**)&w16_0, g_w16);

    // One-time host objects (created on the uncaptured correctness call;
    // identical op sequence is recorded every call -> deterministic work).
    static cudaStream_t s1 = nullptr;
    static cudaEvent_t evF, evA, evZ1, evP1;
    if (!s1) {
        cudaStreamCreateWithFlags(&s1, cudaStreamNonBlocking);
        cudaEventCreateWithFlags(&evF, cudaEventDisableTiming);
        cudaEventCreateWithFlags(&evA, cudaEventDisableTiming);
        cudaEventCreateWithFlags(&evZ1, cudaEventDisableTiming);
        cudaEventCreateWithFlags(&evP1, cudaEventDisableTiming);
    }

    const int GEMM_GRID = (NN + GEMM_M - 1) / GEMM_M;  // 782

    // Fork side stream off the capture origin.
    cudaEventRecord(evF, 0);
    cudaStreamWaitEvent(s1, evF, 0);

    // Main chain: CSR build (g_indeg zero on entry).
    k_deg<<<(EE + 255) / 256, 256>>>(dst);                          // 0
    k_scan_block<<<SCAN_NB, SCAN_B>>>();                            // 1 (+dinv)
    k_scan_fill<<<SCAN_NB, SCAN_B>>>();                             // 2
    k_fill<<<(EE + 255) / 256, 256>>>(src, dst);                    // 3 <- probe

    // Side chain: W convert + gstart, then graph-independent GEMM1.
    k_wcvt_gstart<<<17, 256, 0, s1>>>(W1, W2, batch);
    k_gemm<<<GEMM_GRID, 256, 0, s1>>>(x, w16_0);
    cudaEventRecord(evA, s1);

    // Join: gather1 needs CSR (main) + zws (side).
    cudaStreamWaitEvent(0, evA, 0);
    k_gather<<<(NN + 3) / 4, 128>>>(b1, alpha, z1);
    cudaEventRecord(evZ1, 0);

    // Side: pool layer-1 half overlaps GEMM2+gather2.
    cudaStreamWaitEvent(s1, evZ1, 0);
    k_pool<<<GG, 128, 0, s1>>>(z1, pool, 0);
    cudaEventRecord(evP1, s1);

    // Main: layer 2.
    k_gemm<<<GEMM_GRID, 256>>>(z1, w16_0 + DD * HH);
    k_gather<<<(NN + 3) / 4, 128>>>(b2, alpha, out);
    cudaStreamWaitEvent(0, evP1, 0);
    k_pool<<<GG, 128>>>(out, pool, HH);   // joins side; last node on main
}